// round 1
// baseline (speedup 1.0000x reference)
#include <cuda_runtime.h>
#include <cuda_bf16.h>

// Problem shapes (fixed by the dataset)
#define NMAX  100000
#define D_IN  128
#define D_OUT 32

// Scratch: h = relu(X@W), hp = unscaled segment-sum accumulator.
__device__ float g_h [NMAX * D_OUT];
__device__ float g_hp[NMAX * D_OUT];

// ---------------------------------------------------------------------------
// Kernel 1: h = relu(X @ W).  Block = 256 threads, tile = 32 rows.
// W (128x32 = 16KB) and an X tile (32x128, padded) staged in smem.
// Each thread computes a 1x4 output chunk.
// ---------------------------------------------------------------------------
__global__ __launch_bounds__(256) void gemm_relu_kernel(
    const float* __restrict__ X, const float* __restrict__ W, int n)
{
    __shared__ float Xs[32 * 132];     // padded stride 132 -> conflict-free
    __shared__ float Ws[128 * 32];

    const int tid = threadIdx.x;

    // Load W (coalesced)
    #pragma unroll
    for (int i = tid; i < 128 * 32; i += 256) Ws[i] = W[i];

    const int rowbase = blockIdx.x * 32;

    // Load X tile as float4 (32 rows x 32 float4)
    const float4* X4 = reinterpret_cast<const float4*>(X) + (size_t)rowbase * 32;
    #pragma unroll
    for (int i = tid; i < 32 * 32; i += 256) {
        int r = i >> 5, c = i & 31;
        float4 v = make_float4(0.f, 0.f, 0.f, 0.f);
        if (rowbase + r < n) v = X4[r * 32 + c];
        float* d = &Xs[r * 132 + c * 4];
        d[0] = v.x; d[1] = v.y; d[2] = v.z; d[3] = v.w;
    }
    __syncthreads();

    const int row = tid >> 3;          // 0..31
    const int col = (tid & 7) * 4;     // 0..28

    float a0 = 0.f, a1 = 0.f, a2 = 0.f, a3 = 0.f;
    #pragma unroll 8
    for (int k = 0; k < 128; k++) {
        float x = Xs[row * 132 + k];
        float4 w = *reinterpret_cast<const float4*>(&Ws[k * 32 + col]);
        a0 = fmaf(x, w.x, a0);
        a1 = fmaf(x, w.y, a1);
        a2 = fmaf(x, w.z, a2);
        a3 = fmaf(x, w.w, a3);
    }

    const int gr = rowbase + row;
    if (gr < n) {
        float4 o;
        o.x = fmaxf(a0, 0.f); o.y = fmaxf(a1, 0.f);
        o.z = fmaxf(a2, 0.f); o.w = fmaxf(a3, 0.f);
        *reinterpret_cast<float4*>(&g_h[gr * D_OUT + col]) = o;
    }
}

// ---------------------------------------------------------------------------
// Kernel 2: scatter.  4 lanes per edge; lane p handles floats [p*8, p*8+8)
// of the 32-float row, i.e. one full 32B sector (no sector over-fetch).
// hp[row] += decay1[time] * h[col] via red.global.add.v4.f32.
// ---------------------------------------------------------------------------
__global__ __launch_bounds__(256) void scatter_kernel(
    const int* __restrict__ erow, const int* __restrict__ ecol,
    const int* __restrict__ etime, const float* __restrict__ dw1, int E)
{
    const int gid = blockIdx.x * 256 + threadIdx.x;
    const int e = gid >> 2;
    const int p = gid & 3;
    if (e >= E) return;

    const int r = __ldg(erow + e);
    const int c = __ldg(ecol + e);
    const int t = __ldg(etime + e);
    const float d = __ldg(dw1 + t);

    const float4* src = reinterpret_cast<const float4*>(g_h + c * D_OUT + p * 8);
    float4 v0 = src[0];
    float4 v1 = src[1];
    v0.x *= d; v0.y *= d; v0.z *= d; v0.w *= d;
    v1.x *= d; v1.y *= d; v1.z *= d; v1.w *= d;

    float* dst = g_hp + r * D_OUT + p * 8;
    asm volatile("red.global.add.v4.f32 [%0], {%1,%2,%3,%4};"
                 :: "l"(dst), "f"(v0.x), "f"(v0.y), "f"(v0.z), "f"(v0.w)
                 : "memory");
    asm volatile("red.global.add.v4.f32 [%0], {%1,%2,%3,%4};"
                 :: "l"(dst + 4), "f"(v1.x), "f"(v1.y), "f"(v1.z), "f"(v1.w)
                 : "memory");
}

// ---------------------------------------------------------------------------
// Kernel 3: out = decay2[60*obs - arrive - 1] * hp   (float4-grained)
// ---------------------------------------------------------------------------
__global__ __launch_bounds__(256) void scale_kernel(
    const int* __restrict__ arrive, const float* __restrict__ dw2,
    const int* __restrict__ obs_ptr, float* __restrict__ out, int n)
{
    const int gid = blockIdx.x * 256 + threadIdx.x;   // over n*8 float4 chunks
    if (gid >= n * 8) return;
    const int node = gid >> 3;
    const int obs = obs_ptr ? __ldg(obs_ptr) : 60;
    const int idx = 60 * obs - __ldg(arrive + node) - 1;
    const float w = __ldg(dw2 + idx);

    float4 v = reinterpret_cast<const float4*>(g_hp)[gid];
    v.x *= w; v.y *= w; v.z *= w; v.w *= w;
    reinterpret_cast<float4*>(out)[gid] = v;
}

// ---------------------------------------------------------------------------
// Launch
// inputs: 0 input[N,128] f32, 1 W[128,32] f32, 2 decay_weight1[3600] f32,
//         3 decay_weight2[3600] f32, 4 edge_row[E] i32, 5 edge_col[E] i32,
//         6 edge_time[E] i32, 7 arrive_time[N] i32, 8 observation_time i32
// output: h_prime [N,32] f32
// ---------------------------------------------------------------------------
extern "C" void kernel_launch(void* const* d_in, const int* in_sizes, int n_in,
                              void* d_out, int out_size)
{
    const float* X    = (const float*)d_in[0];
    const float* W    = (const float*)d_in[1];
    const float* dw1  = (const float*)d_in[2];
    const float* dw2  = (const float*)d_in[3];
    const int*  erow  = (const int*)d_in[4];
    const int*  ecol  = (const int*)d_in[5];
    const int*  etime = (const int*)d_in[6];
    const int*  arrive= (const int*)d_in[7];
    const int*  obs_p = (n_in > 8) ? (const int*)d_in[8] : nullptr;

    const int n = in_sizes[7];          // number of nodes
    const int E = in_sizes[4];          // number of edges

    // Zero the accumulator (captured as a memset node in the graph)
    void* hp_ptr = nullptr;
    cudaGetSymbolAddress(&hp_ptr, g_hp);
    cudaMemsetAsync(hp_ptr, 0, (size_t)n * D_OUT * sizeof(float));

    // 1) h = relu(X @ W)
    gemm_relu_kernel<<<(n + 31) / 32, 256>>>(X, W, n);

    // 2) scatter: hp[row] += decay1[time] * h[col]
    const long long sthreads = (long long)E * 4;
    scatter_kernel<<<(int)((sthreads + 255) / 256), 256>>>(erow, ecol, etime, dw1, E);

    // 3) out = decay2[win] * hp
    const long long cthreads = (long long)n * 8;
    scale_kernel<<<(int)((cthreads + 255) / 256), 256>>>(arrive, dw2, obs_p, (float*)d_out, n);
}

// round 2
// speedup vs baseline: 1.2725x; 1.2725x over previous
#include <cuda_runtime.h>
#include <cuda_bf16.h>

#define NMAX  100000
#define D_IN  128
#define D_OUT 32

__device__ float g_h [NMAX * D_OUT];
__device__ float g_hp[NMAX * D_OUT];

__device__ __forceinline__ unsigned long long fma2(
    unsigned long long a, unsigned long long b, unsigned long long c)
{
    unsigned long long d;
    asm("fma.rn.f32x2 %0, %1, %2, %3;" : "=l"(d) : "l"(a), "l"(b), "l"(c));
    return d;
}

__device__ __forceinline__ unsigned long long pack2(float x)
{
    unsigned long long d;
    asm("mov.b64 %0, {%1, %1};" : "=l"(d) : "f"(x));
    return d;
}

// ---------------------------------------------------------------------------
// Kernel 1: h = relu(X @ W).
// Block = 256 threads, tile = 256 rows x 32 cols, k chunked by 32.
// Thread (rowgrp = tid>>3, colgrp = tid&7) computes 8 rows x 4 cols via
// packed f32x2 FMAs (rows paired). X tile stored TRANSPOSED + XOR-swizzled:
//   phys(k, r) = k*256 + 4*((r>>2) ^ ((k>>2)&7)) + (r&3)
// -> conflict-free transpose stores AND conflict-free LDS.128 x-loads.
// ---------------------------------------------------------------------------
__global__ __launch_bounds__(256, 3) void gemm_relu_kernel(
    const float* __restrict__ X, const float* __restrict__ W, int n)
{
    extern __shared__ float smemf[];
    float* Xs = smemf;          // 32 * 256 floats (32 KB)
    float* Ws = smemf + 8192;   // 128 * 32 floats (16 KB)

    const int tid = threadIdx.x;
    const int rowbase = blockIdx.x * 256;

    // Load W once (coalesced)
    #pragma unroll
    for (int i = tid; i < 128 * 32; i += 256) Ws[i] = W[i];

    const int rowgrp = tid >> 3;        // 0..31  -> rows rowgrp*8 .. +7
    const int colgrp = tid & 7;         // 0..7   -> cols colgrp*4 .. +3
    const int r0 = rowgrp * 8;
    const int c0 = colgrp * 4;
    const int rg2 = rowgrp * 2;         // base row-block (4-row units)

    unsigned long long acc[4][4];
    #pragma unroll
    for (int rp = 0; rp < 4; rp++)
        #pragma unroll
        for (int j = 0; j < 4; j++) acc[rp][j] = 0ULL;

    const float4* X4 = reinterpret_cast<const float4*>(X);

    // load indices: i = s*256 + tid ; r = i>>3 (row 0..255), c = i&7 (k-float4)
    const int lr = tid >> 3;            // same as rowgrp: rows handled per pass
    const int lc = tid & 7;

    #pragma unroll 1
    for (int chunk = 0; chunk < 4; chunk++) {
        // ---- load + transpose 256 rows x 32 k into Xs ----
        #pragma unroll
        for (int s = 0; s < 8; s++) {
            const int r = lr + s * 32;              // 0..255
            const int c = lc;                       // k-float4 within chunk
            float4 v = make_float4(0.f, 0.f, 0.f, 0.f);
            if (rowbase + r < n)
                v = X4[(size_t)(rowbase + r) * 32 + chunk * 8 + c];
            // store k = 4c+j at swizzled position; swizzle mask = c
            const int base = 4 * ((r >> 2) ^ c) + (r & 3);
            Xs[(4 * c + 0) * 256 + base] = v.x;
            Xs[(4 * c + 1) * 256 + base] = v.y;
            Xs[(4 * c + 2) * 256 + base] = v.z;
            Xs[(4 * c + 3) * 256 + base] = v.w;
        }
        __syncthreads();

        // ---- compute 32 k-steps ----
        #pragma unroll 4
        for (int kl = 0; kl < 32; kl++) {
            const int m = (kl >> 2) & 7;
            const ulonglong2 pa = *reinterpret_cast<const ulonglong2*>(
                &Xs[kl * 256 + (((rg2)     ^ m) << 2)]);   // rows r0..r0+3
            const ulonglong2 pb = *reinterpret_cast<const ulonglong2*>(
                &Xs[kl * 256 + (((rg2 + 1) ^ m) << 2)]);   // rows r0+4..r0+7

            const int kg = chunk * 32 + kl;
            const float4 w = *reinterpret_cast<const float4*>(&Ws[kg * 32 + c0]);
            unsigned long long wp0 = pack2(w.x);
            unsigned long long wp1 = pack2(w.y);
            unsigned long long wp2 = pack2(w.z);
            unsigned long long wp3 = pack2(w.w);

            acc[0][0] = fma2(pa.x, wp0, acc[0][0]);
            acc[0][1] = fma2(pa.x, wp1, acc[0][1]);
            acc[0][2] = fma2(pa.x, wp2, acc[0][2]);
            acc[0][3] = fma2(pa.x, wp3, acc[0][3]);
            acc[1][0] = fma2(pa.y, wp0, acc[1][0]);
            acc[1][1] = fma2(pa.y, wp1, acc[1][1]);
            acc[1][2] = fma2(pa.y, wp2, acc[1][2]);
            acc[1][3] = fma2(pa.y, wp3, acc[1][3]);
            acc[2][0] = fma2(pb.x, wp0, acc[2][0]);
            acc[2][1] = fma2(pb.x, wp1, acc[2][1]);
            acc[2][2] = fma2(pb.x, wp2, acc[2][2]);
            acc[2][3] = fma2(pb.x, wp3, acc[2][3]);
            acc[3][0] = fma2(pb.y, wp0, acc[3][0]);
            acc[3][1] = fma2(pb.y, wp1, acc[3][1]);
            acc[3][2] = fma2(pb.y, wp2, acc[3][2]);
            acc[3][3] = fma2(pb.y, wp3, acc[3][3]);
        }
        __syncthreads();
    }

    // ---- epilogue: unpack, relu, store ----
    #pragma unroll
    for (int rp = 0; rp < 4; rp++) {
        float lo[4], hi[4];
        #pragma unroll
        for (int j = 0; j < 4; j++) {
            float l, h;
            asm("mov.b64 {%0, %1}, %2;" : "=f"(l), "=f"(h) : "l"(acc[rp][j]));
            lo[j] = fmaxf(l, 0.f);
            hi[j] = fmaxf(h, 0.f);
        }
        const int grl = rowbase + r0 + 2 * rp;
        if (grl < n)
            *reinterpret_cast<float4*>(&g_h[grl * D_OUT + c0]) =
                make_float4(lo[0], lo[1], lo[2], lo[3]);
        if (grl + 1 < n)
            *reinterpret_cast<float4*>(&g_h[(grl + 1) * D_OUT + c0]) =
                make_float4(hi[0], hi[1], hi[2], hi[3]);
    }
}

// ---------------------------------------------------------------------------
// Kernel 2: scatter. 4 lanes per edge; lane p handles one full 32B sector.
// hp[row] += decay1[time] * h[col] via red.global.add.v4.f32.
// ---------------------------------------------------------------------------
__global__ __launch_bounds__(256) void scatter_kernel(
    const int* __restrict__ erow, const int* __restrict__ ecol,
    const int* __restrict__ etime, const float* __restrict__ dw1, int E)
{
    const int gid = blockIdx.x * 256 + threadIdx.x;
    const int e = gid >> 2;
    const int p = gid & 3;
    if (e >= E) return;

    const int r = __ldg(erow + e);
    const int c = __ldg(ecol + e);
    const int t = __ldg(etime + e);
    const float d = __ldg(dw1 + t);

    const float4* src = reinterpret_cast<const float4*>(g_h + c * D_OUT + p * 8);
    float4 v0 = src[0];
    float4 v1 = src[1];
    v0.x *= d; v0.y *= d; v0.z *= d; v0.w *= d;
    v1.x *= d; v1.y *= d; v1.z *= d; v1.w *= d;

    float* dst = g_hp + r * D_OUT + p * 8;
    asm volatile("red.global.add.v4.f32 [%0], {%1,%2,%3,%4};"
                 :: "l"(dst), "f"(v0.x), "f"(v0.y), "f"(v0.z), "f"(v0.w)
                 : "memory");
    asm volatile("red.global.add.v4.f32 [%0], {%1,%2,%3,%4};"
                 :: "l"(dst + 4), "f"(v1.x), "f"(v1.y), "f"(v1.z), "f"(v1.w)
                 : "memory");
}

// ---------------------------------------------------------------------------
// Kernel 3: out = decay2[60*obs - arrive - 1] * hp
// ---------------------------------------------------------------------------
__global__ __launch_bounds__(256) void scale_kernel(
    const int* __restrict__ arrive, const float* __restrict__ dw2,
    const int* __restrict__ obs_ptr, float* __restrict__ out, int n)
{
    const int gid = blockIdx.x * 256 + threadIdx.x;
    if (gid >= n * 8) return;
    const int node = gid >> 3;
    const int obs = obs_ptr ? __ldg(obs_ptr) : 60;
    const int idx = 60 * obs - __ldg(arrive + node) - 1;
    const float w = __ldg(dw2 + idx);

    float4 v = reinterpret_cast<const float4*>(g_hp)[gid];
    v.x *= w; v.y *= w; v.z *= w; v.w *= w;
    reinterpret_cast<float4*>(out)[gid] = v;
}

// ---------------------------------------------------------------------------
extern "C" void kernel_launch(void* const* d_in, const int* in_sizes, int n_in,
                              void* d_out, int out_size)
{
    const float* X    = (const float*)d_in[0];
    const float* W    = (const float*)d_in[1];
    const float* dw1  = (const float*)d_in[2];
    const float* dw2  = (const float*)d_in[3];
    const int*  erow  = (const int*)d_in[4];
    const int*  ecol  = (const int*)d_in[5];
    const int*  etime = (const int*)d_in[6];
    const int*  arrive= (const int*)d_in[7];
    const int*  obs_p = (n_in > 8) ? (const int*)d_in[8] : nullptr;

    const int n = in_sizes[7];
    const int E = in_sizes[4];

    void* hp_ptr = nullptr;
    cudaGetSymbolAddress(&hp_ptr, g_hp);
    cudaMemsetAsync(hp_ptr, 0, (size_t)n * D_OUT * sizeof(float));

    const int smem = (8192 + 4096) * sizeof(float);   // 48 KB
    gemm_relu_kernel<<<(n + 255) / 256, 256, smem>>>(X, W, n);

    const long long sthreads = (long long)E * 4;
    scatter_kernel<<<(int)((sthreads + 255) / 256), 256>>>(erow, ecol, etime, dw1, E);

    const long long cthreads = (long long)n * 8;
    scale_kernel<<<(int)((cthreads + 255) / 256), 256>>>(arrive, dw2, obs_p, (float*)d_out, n);
}

// round 3
// speedup vs baseline: 1.3334x; 1.0479x over previous
#include <cuda_runtime.h>
#include <cuda_bf16.h>

#define NMAX  100000
#define D_IN  128
#define D_OUT 32

__device__ float g_h [NMAX * D_OUT];
__device__ float g_w2[NMAX];

__device__ __forceinline__ unsigned long long fma2(
    unsigned long long a, unsigned long long b, unsigned long long c)
{
    unsigned long long d;
    asm("fma.rn.f32x2 %0, %1, %2, %3;" : "=l"(d) : "l"(a), "l"(b), "l"(c));
    return d;
}

__device__ __forceinline__ unsigned long long pack2(float x)
{
    unsigned long long d;
    asm("mov.b64 %0, {%1, %1};" : "=l"(d) : "f"(x));
    return d;
}

// ---------------------------------------------------------------------------
// Kernel 1: h = relu(X @ W), plus per-node w2 = dw2[60*obs - arrive - 1].
// Block = 256 threads, tile = 128 rows, k chunked by 32, register-prefetch
// double buffering of the X tile (LDG for chunk i+1 issued before compute of
// chunk i). X tile transposed + XOR-swizzled:
//   phys(k, r) = k*128 + 4*((r>>2) ^ ((k>>2)&7)) + (r&3)
// -> conflict-free on both transpose stores and LDS.128 compute loads.
// Thread (rowgrp=tid>>3, colgrp=tid&7): 4 rows x 4 cols via f32x2 FMAs.
// ---------------------------------------------------------------------------
__global__ __launch_bounds__(256, 3) void gemm_relu_kernel(
    const float* __restrict__ X, const float* __restrict__ W,
    const int* __restrict__ arrive, const float* __restrict__ dw2,
    const int* __restrict__ obs_ptr, int n)
{
    __shared__ float Xs[32 * 128];    // 16 KB, transposed k-major
    __shared__ float Ws[128 * 32];    // 16 KB

    const int tid = threadIdx.x;
    const int rowbase = blockIdx.x * 128;

    // ---- w2 epilogue-precompute (independent, overlaps everything) ----
    if (tid < 128) {
        const int node = rowbase + tid;
        if (node < n) {
            const int obs = obs_ptr ? __ldg(obs_ptr) : 60;
            const int idx = 60 * obs - __ldg(arrive + node) - 1;
            g_w2[node] = __ldg(dw2 + idx);
        }
    }

    const float4* X4 = reinterpret_cast<const float4*>(X);
    const int lr = tid >> 3;          // loader row within 32-row pass
    const int lc = tid & 7;           // loader k-float4

    // ---- prefetch chunk 0 ----
    float4 pf[4];
    #pragma unroll
    for (int s = 0; s < 4; s++) {
        const int r = lr + s * 32 + ((tid >> 3) >= 32 ? 0 : 0);
        const int rr = (s * 256 + tid) >> 3;        // 0..127
        float4 v = make_float4(0.f, 0.f, 0.f, 0.f);
        if (rowbase + rr < n) v = X4[(size_t)(rowbase + rr) * 32 + lc];
        pf[s] = v;
        (void)r;
    }

    // ---- load W (coalesced float4) ----
    const float4* W4 = reinterpret_cast<const float4*>(W);
    float4* Ws4 = reinterpret_cast<float4*>(Ws);
    #pragma unroll
    for (int i = tid; i < 1024; i += 256) Ws4[i] = W4[i];

    const int rowgrp = tid >> 3;      // 0..31 -> rows rowgrp*4 .. +3
    const int colgrp = tid & 7;       // 0..7  -> cols colgrp*4 .. +3
    const int c0 = colgrp * 4;

    unsigned long long acc[2][4];
    #pragma unroll
    for (int rp = 0; rp < 2; rp++)
        #pragma unroll
        for (int j = 0; j < 4; j++) acc[rp][j] = 0ULL;

    #pragma unroll 1
    for (int chunk = 0; chunk < 4; chunk++) {
        // ---- store prefetched tile (transposed + swizzled) ----
        #pragma unroll
        for (int s = 0; s < 4; s++) {
            const int rr = (s * 256 + tid) >> 3;    // row 0..127
            const int base = 4 * ((rr >> 2) ^ lc) + (rr & 3);
            Xs[(4 * lc + 0) * 128 + base] = pf[s].x;
            Xs[(4 * lc + 1) * 128 + base] = pf[s].y;
            Xs[(4 * lc + 2) * 128 + base] = pf[s].z;
            Xs[(4 * lc + 3) * 128 + base] = pf[s].w;
        }
        __syncthreads();

        // ---- prefetch next chunk (overlaps compute) ----
        if (chunk < 3) {
            #pragma unroll
            for (int s = 0; s < 4; s++) {
                const int rr = (s * 256 + tid) >> 3;
                float4 v = make_float4(0.f, 0.f, 0.f, 0.f);
                if (rowbase + rr < n)
                    v = X4[(size_t)(rowbase + rr) * 32 + (chunk + 1) * 8 + lc];
                pf[s] = v;
            }
        }

        // ---- compute 32 k-steps ----
        #pragma unroll 4
        for (int kl = 0; kl < 32; kl++) {
            const int m = (kl >> 2) & 7;
            const ulonglong2 x2 = *reinterpret_cast<const ulonglong2*>(
                &Xs[kl * 128 + ((rowgrp ^ m) << 2)]);   // rows 4rg..4rg+3

            const int kg = chunk * 32 + kl;
            const float4 w = *reinterpret_cast<const float4*>(&Ws[kg * 32 + c0]);
            const unsigned long long wp0 = pack2(w.x);
            const unsigned long long wp1 = pack2(w.y);
            const unsigned long long wp2 = pack2(w.z);
            const unsigned long long wp3 = pack2(w.w);

            acc[0][0] = fma2(x2.x, wp0, acc[0][0]);
            acc[0][1] = fma2(x2.x, wp1, acc[0][1]);
            acc[0][2] = fma2(x2.x, wp2, acc[0][2]);
            acc[0][3] = fma2(x2.x, wp3, acc[0][3]);
            acc[1][0] = fma2(x2.y, wp0, acc[1][0]);
            acc[1][1] = fma2(x2.y, wp1, acc[1][1]);
            acc[1][2] = fma2(x2.y, wp2, acc[1][2]);
            acc[1][3] = fma2(x2.y, wp3, acc[1][3]);
        }
        __syncthreads();
    }

    // ---- epilogue: unpack, relu, store 4 rows x 4 cols ----
    #pragma unroll
    for (int rp = 0; rp < 2; rp++) {
        float lo[4], hi[4];
        #pragma unroll
        for (int j = 0; j < 4; j++) {
            float l, h;
            asm("mov.b64 {%0, %1}, %2;" : "=f"(l), "=f"(h) : "l"(acc[rp][j]));
            lo[j] = fmaxf(l, 0.f);
            hi[j] = fmaxf(h, 0.f);
        }
        const int grl = rowbase + rowgrp * 4 + 2 * rp;
        if (grl < n)
            *reinterpret_cast<float4*>(&g_h[grl * D_OUT + c0]) =
                make_float4(lo[0], lo[1], lo[2], lo[3]);
        if (grl + 1 < n)
            *reinterpret_cast<float4*>(&g_h[(grl + 1) * D_OUT + c0]) =
                make_float4(hi[0], hi[1], hi[2], hi[3]);
    }
}

// ---------------------------------------------------------------------------
// Kernel 2: fused scatter. 4 lanes per edge; lane p handles one 32B sector.
// out[row] += dw1[time] * w2[row] * h[col]   via red.global.add.v4.f32.
// ---------------------------------------------------------------------------
__global__ __launch_bounds__(256) void scatter_kernel(
    const int* __restrict__ erow, const int* __restrict__ ecol,
    const int* __restrict__ etime, const float* __restrict__ dw1,
    float* __restrict__ out, int E)
{
    const int gid = blockIdx.x * 256 + threadIdx.x;
    const int e = gid >> 2;
    const int p = gid & 3;
    if (e >= E) return;

    const int r = __ldg(erow + e);
    const int c = __ldg(ecol + e);
    const int t = __ldg(etime + e);
    const float d = __ldg(dw1 + t) * __ldg(g_w2 + r);

    const float4* src = reinterpret_cast<const float4*>(g_h + c * D_OUT + p * 8);
    float4 v0 = src[0];
    float4 v1 = src[1];
    v0.x *= d; v0.y *= d; v0.z *= d; v0.w *= d;
    v1.x *= d; v1.y *= d; v1.z *= d; v1.w *= d;

    float* dst = out + r * D_OUT + p * 8;
    asm volatile("red.global.add.v4.f32 [%0], {%1,%2,%3,%4};"
                 :: "l"(dst), "f"(v0.x), "f"(v0.y), "f"(v0.z), "f"(v0.w)
                 : "memory");
    asm volatile("red.global.add.v4.f32 [%0], {%1,%2,%3,%4};"
                 :: "l"(dst + 4), "f"(v1.x), "f"(v1.y), "f"(v1.z), "f"(v1.w)
                 : "memory");
}

// ---------------------------------------------------------------------------
extern "C" void kernel_launch(void* const* d_in, const int* in_sizes, int n_in,
                              void* d_out, int out_size)
{
    const float* X    = (const float*)d_in[0];
    const float* W    = (const float*)d_in[1];
    const float* dw1  = (const float*)d_in[2];
    const float* dw2  = (const float*)d_in[3];
    const int*  erow  = (const int*)d_in[4];
    const int*  ecol  = (const int*)d_in[5];
    const int*  etime = (const int*)d_in[6];
    const int*  arrive= (const int*)d_in[7];
    const int*  obs_p = (n_in > 8) ? (const int*)d_in[8] : nullptr;

    const int n = in_sizes[7];
    const int E = in_sizes[4];

    // Zero the output (accumulated directly by the fused scatter)
    cudaMemsetAsync(d_out, 0, (size_t)out_size * sizeof(float));

    // 1) h = relu(X @ W) + w2 precompute
    gemm_relu_kernel<<<(n + 127) / 128, 256>>>(X, W, arrive, dw2, obs_p, n);

    // 2) fused scatter: out[row] += dw1[t] * w2[row] * h[col]
    const long long sthreads = (long long)E * 4;
    scatter_kernel<<<(int)((sthreads + 255) / 256), 256>>>(
        erow, ecol, etime, dw1, (float*)d_out, E);
}

// round 4
// speedup vs baseline: 1.4562x; 1.0921x over previous
#include <cuda_runtime.h>
#include <cuda_bf16.h>

#define NMAX  100000
#define D_IN  128
#define D_OUT 32

__device__ float g_h [NMAX * D_OUT];
__device__ float g_w2[NMAX];

__device__ __forceinline__ unsigned long long fma2(
    unsigned long long a, unsigned long long b, unsigned long long c)
{
    unsigned long long d;
    asm("fma.rn.f32x2 %0, %1, %2, %3;" : "=l"(d) : "l"(a), "l"(b), "l"(c));
    return d;
}

__device__ __forceinline__ unsigned long long pack2(float x)
{
    unsigned long long d;
    asm("mov.b64 %0, {%1, %1};" : "=l"(d) : "f"(x));
    return d;
}

// ---------------------------------------------------------------------------
// Kernel 1: h = relu(X @ W), plus per-node w2 = dw2[60*obs - arrive - 1].
// (unchanged from R3 — isolate the scatter change)
// ---------------------------------------------------------------------------
__global__ __launch_bounds__(256, 3) void gemm_relu_kernel(
    const float* __restrict__ X, const float* __restrict__ W,
    const int* __restrict__ arrive, const float* __restrict__ dw2,
    const int* __restrict__ obs_ptr, int n)
{
    __shared__ float Xs[32 * 128];
    __shared__ float Ws[128 * 32];

    const int tid = threadIdx.x;
    const int rowbase = blockIdx.x * 128;

    if (tid < 128) {
        const int node = rowbase + tid;
        if (node < n) {
            const int obs = obs_ptr ? __ldg(obs_ptr) : 60;
            const int idx = 60 * obs - __ldg(arrive + node) - 1;
            g_w2[node] = __ldg(dw2 + idx);
        }
    }

    const float4* X4 = reinterpret_cast<const float4*>(X);
    const int lc = tid & 7;

    float4 pf[4];
    #pragma unroll
    for (int s = 0; s < 4; s++) {
        const int rr = (s * 256 + tid) >> 3;
        float4 v = make_float4(0.f, 0.f, 0.f, 0.f);
        if (rowbase + rr < n) v = X4[(size_t)(rowbase + rr) * 32 + lc];
        pf[s] = v;
    }

    const float4* W4 = reinterpret_cast<const float4*>(W);
    float4* Ws4 = reinterpret_cast<float4*>(Ws);
    #pragma unroll
    for (int i = tid; i < 1024; i += 256) Ws4[i] = W4[i];

    const int rowgrp = tid >> 3;
    const int colgrp = tid & 7;
    const int c0 = colgrp * 4;

    unsigned long long acc[2][4];
    #pragma unroll
    for (int rp = 0; rp < 2; rp++)
        #pragma unroll
        for (int j = 0; j < 4; j++) acc[rp][j] = 0ULL;

    #pragma unroll 1
    for (int chunk = 0; chunk < 4; chunk++) {
        #pragma unroll
        for (int s = 0; s < 4; s++) {
            const int rr = (s * 256 + tid) >> 3;
            const int base = 4 * ((rr >> 2) ^ lc) + (rr & 3);
            Xs[(4 * lc + 0) * 128 + base] = pf[s].x;
            Xs[(4 * lc + 1) * 128 + base] = pf[s].y;
            Xs[(4 * lc + 2) * 128 + base] = pf[s].z;
            Xs[(4 * lc + 3) * 128 + base] = pf[s].w;
        }
        __syncthreads();

        if (chunk < 3) {
            #pragma unroll
            for (int s = 0; s < 4; s++) {
                const int rr = (s * 256 + tid) >> 3;
                float4 v = make_float4(0.f, 0.f, 0.f, 0.f);
                if (rowbase + rr < n)
                    v = X4[(size_t)(rowbase + rr) * 32 + (chunk + 1) * 8 + lc];
                pf[s] = v;
            }
        }

        #pragma unroll 4
        for (int kl = 0; kl < 32; kl++) {
            const int m = (kl >> 2) & 7;
            const ulonglong2 x2 = *reinterpret_cast<const ulonglong2*>(
                &Xs[kl * 128 + ((rowgrp ^ m) << 2)]);

            const int kg = chunk * 32 + kl;
            const float4 w = *reinterpret_cast<const float4*>(&Ws[kg * 32 + c0]);
            const unsigned long long wp0 = pack2(w.x);
            const unsigned long long wp1 = pack2(w.y);
            const unsigned long long wp2 = pack2(w.z);
            const unsigned long long wp3 = pack2(w.w);

            acc[0][0] = fma2(x2.x, wp0, acc[0][0]);
            acc[0][1] = fma2(x2.x, wp1, acc[0][1]);
            acc[0][2] = fma2(x2.x, wp2, acc[0][2]);
            acc[0][3] = fma2(x2.x, wp3, acc[0][3]);
            acc[1][0] = fma2(x2.y, wp0, acc[1][0]);
            acc[1][1] = fma2(x2.y, wp1, acc[1][1]);
            acc[1][2] = fma2(x2.y, wp2, acc[1][2]);
            acc[1][3] = fma2(x2.y, wp3, acc[1][3]);
        }
        __syncthreads();
    }

    #pragma unroll
    for (int rp = 0; rp < 2; rp++) {
        float lo[4], hi[4];
        #pragma unroll
        for (int j = 0; j < 4; j++) {
            float l, h;
            asm("mov.b64 {%0, %1}, %2;" : "=f"(l), "=f"(h) : "l"(acc[rp][j]));
            lo[j] = fmaxf(l, 0.f);
            hi[j] = fmaxf(h, 0.f);
        }
        const int grl = rowbase + rowgrp * 4 + 2 * rp;
        if (grl < n)
            *reinterpret_cast<float4*>(&g_h[grl * D_OUT + c0]) =
                make_float4(lo[0], lo[1], lo[2], lo[3]);
        if (grl + 1 < n)
            *reinterpret_cast<float4*>(&g_h[(grl + 1) * D_OUT + c0]) =
                make_float4(hi[0], hi[1], hi[2], hi[3]);
    }
}

// ---------------------------------------------------------------------------
// Kernel 2: fused scatter. 8 lanes per edge; lane p owns one float4 (16B).
// One LDG.128 + one RED.128 per lane -> 2 wavefronts + 2 mem-ops per edge
// (half of the 4-lane variant).
// out[row] += dw1[time] * w2[row] * h[col]
// ---------------------------------------------------------------------------
__global__ __launch_bounds__(256) void scatter_kernel(
    const int* __restrict__ erow, const int* __restrict__ ecol,
    const int* __restrict__ etime, const float* __restrict__ dw1,
    float* __restrict__ out, int E)
{
    const int gid = blockIdx.x * 256 + threadIdx.x;
    const int e = gid >> 3;
    const int p = gid & 7;
    if (e >= E) return;

    const int r = __ldg(erow + e);
    const int c = __ldg(ecol + e);
    const int t = __ldg(etime + e);
    const float d = __ldg(dw1 + t) * __ldg(g_w2 + r);

    float4 v = *reinterpret_cast<const float4*>(g_h + c * D_OUT + p * 4);
    v.x *= d; v.y *= d; v.z *= d; v.w *= d;

    float* dst = out + r * D_OUT + p * 4;
    asm volatile("red.global.add.v4.f32 [%0], {%1,%2,%3,%4};"
                 :: "l"(dst), "f"(v.x), "f"(v.y), "f"(v.z), "f"(v.w)
                 : "memory");
}

// ---------------------------------------------------------------------------
extern "C" void kernel_launch(void* const* d_in, const int* in_sizes, int n_in,
                              void* d_out, int out_size)
{
    const float* X    = (const float*)d_in[0];
    const float* W    = (const float*)d_in[1];
    const float* dw1  = (const float*)d_in[2];
    const float* dw2  = (const float*)d_in[3];
    const int*  erow  = (const int*)d_in[4];
    const int*  ecol  = (const int*)d_in[5];
    const int*  etime = (const int*)d_in[6];
    const int*  arrive= (const int*)d_in[7];
    const int*  obs_p = (n_in > 8) ? (const int*)d_in[8] : nullptr;

    const int n = in_sizes[7];
    const int E = in_sizes[4];

    cudaMemsetAsync(d_out, 0, (size_t)out_size * sizeof(float));

    gemm_relu_kernel<<<(n + 127) / 128, 256>>>(X, W, arrive, dw2, obs_p, n);

    const long long sthreads = (long long)E * 8;
    scatter_kernel<<<(int)((sthreads + 255) / 256), 256>>>(
        erow, ecol, etime, dw1, (float*)d_out, E);
}